// round 11
// baseline (speedup 1.0000x reference)
#include <cuda_runtime.h>
#include <cuda_bf16.h>
#include <cuda_fp16.h>

// Problem constants (B=8, N=256, H=128)
#define BB 8
#define NN 256
#define HH 128
#define ROWS (BB * NN)        // 2048
#define TIF 16                // i-rows per fused CTA

typedef unsigned long long ull;

// Scratch (allocation-free rule: __device__ globals)
// g_P = 0.5*(node@We1a + be1); g_Q = 0.5*(node@We1b)  (pre-halved for tanh-silu)
__device__ float g_P[ROWS * HH];
__device__ float g_Q[ROWS * HH];

// ---------------- packed f32x2 + MUFU helpers ----------------
__device__ __forceinline__ ull fma2(ull a, ull b, ull c) {
    ull d; asm("fma.rn.f32x2 %0, %1, %2, %3;" : "=l"(d) : "l"(a), "l"(b), "l"(c)); return d;
}
__device__ __forceinline__ ull add2(ull a, ull b) {
    ull d; asm("add.rn.f32x2 %0, %1, %2;" : "=l"(d) : "l"(a), "l"(b)); return d;
}
__device__ __forceinline__ ull mul2(ull a, ull b) {
    ull d; asm("mul.rn.f32x2 %0, %1, %2;" : "=l"(d) : "l"(a), "l"(b)); return d;
}
__device__ __forceinline__ ull pack2(float lo, float hi) {
    ull d; asm("mov.b64 %0, {%1, %2};" : "=l"(d) : "f"(lo), "f"(hi)); return d;
}
__device__ __forceinline__ void unpack2(ull v, float& lo, float& hi) {
    asm("mov.b64 {%0, %1}, %2;" : "=f"(lo), "=f"(hi) : "l"(v));
}
__device__ __forceinline__ float sqrtfast(float x) {
    float y; asm("sqrt.approx.f32 %0, %1;" : "=f"(y) : "f"(x)); return y;
}
__device__ __forceinline__ float fast_sigmoid(float x) {
    float e; asm("ex2.approx.f32 %0, %1;" : "=f"(e) : "f"(-1.4426950408889634f * x));
    float r; asm("rcp.approx.f32 %0, %1;" : "=f"(r) : "f"(1.0f + e));
    return r;
}
// tanh on both fp16 lanes, one MUFU op
__device__ __forceinline__ __half2 tanh2h(__half2 h) {
    unsigned u = *reinterpret_cast<unsigned*>(&h);
    asm("tanh.approx.f16x2 %0, %0;" : "+r"(u));
    return *reinterpret_cast<__half2*>(&u);
}

// ---------------------------------------------------------------------------
// Kernel 1: P' = 0.5*(node@We1a + be1) ; Q' = 0.5*(node@We1b)
// grid 128 x 512 thr, 16 rows/CTA. ENTIRE We1[0:256] (128 KB) staged to smem
// once; inner loop is pure LDS + fma2.
// ---------------------------------------------------------------------------
#define PQ_SMEM (131072 + 8192)
__global__ __launch_bounds__(512, 1)
void k_pq(const float* __restrict__ node,
          const float* __restrict__ We1,
          const float* __restrict__ be1) {
    extern __shared__ __align__(16) char smem_pq[];
    float* wsm = (float*)smem_pq;                 // [e 0..255][k]  128 KB
    ull*   xs2 = (ull*)(smem_pq + 131072);        // [e][p<8]       8 KB

    int row0 = blockIdx.x * 16;
    int tid = threadIdx.x;
    int k = tid & 127;
    int half = (tid >> 7) & 1;
    int rg = tid >> 8;

    {
        const float4* wsrc = (const float4*)We1;
        float4* wdst = (float4*)wsm;
#pragma unroll
        for (int i = 0; i < 16; i++) wdst[tid + i * 512] = wsrc[tid + i * 512];
    }
    {
#pragma unroll
        for (int t = 0; t < 2; t++) {
            int idx = tid + t * 512;
            int e = idx & 127, p = idx >> 7;
            xs2[e * 8 + p] = pack2(node[(row0 + 2 * p) * HH + e],
                                   node[(row0 + 2 * p + 1) * HH + e]);
        }
    }
    __syncthreads();

    const float* W = wsm + half * (HH * HH) + k;
    float bv = half ? 0.0f : be1[k];
    ull acc2[4];
#pragma unroll
    for (int p = 0; p < 4; p++) acc2[p] = pack2(bv, bv);

#pragma unroll 8
    for (int e = 0; e < HH; e++) {
        float w = W[e * HH];
        ull w2 = pack2(w, w);
        ulonglong2 xa = *(const ulonglong2*)&xs2[e * 8 + rg * 4];
        ulonglong2 xb = *(const ulonglong2*)&xs2[e * 8 + rg * 4 + 2];
        acc2[0] = fma2(xa.x, w2, acc2[0]);
        acc2[1] = fma2(xa.y, w2, acc2[1]);
        acc2[2] = fma2(xb.x, w2, acc2[2]);
        acc2[3] = fma2(xb.y, w2, acc2[3]);
    }

    float* dst = half ? g_Q : g_P;
    ull hc = pack2(0.5f, 0.5f);
#pragma unroll
    for (int p = 0; p < 4; p++) {
        float lo, hi; unpack2(mul2(acc2[p], hc), lo, hi);
        int pr = rg * 4 + p;
        dst[(row0 + 2 * pr) * HH + k] = lo;
        dst[(row0 + 2 * pr + 1) * HH + k] = hi;
    }
}

// ---------------------------------------------------------------------------
// Fused kernel: edge aggregation + agg scale + node MLP + residual.
// grid (N/TIF, B) = 128 CTAs, 512 threads.
// Edge: thread = (jh, row-pair ip, k-quad). silu evaluated in fp16:
//   h2 (f32, accurate) -> cvt f16x2 -> tanh.f16x2 (1 MUFU / 2 elems)
//   -> HFMA2 s = h*(1+t) -> HFMA2 macc += m*s ; flush to f32 acc every 8 j.
// Dist row-pairs and mask prepacked (no per-j packs). Tail = R10 form.
// ---------------------------------------------------------------------------
#define QSM_OFF  0          // float[256][128]   131072
#define BSM_OFF  131072     // float[16][128]    8192
#define DSM_OFF  139264     // ull[8][256]       16384  (dist row-pairs)
#define MSM_OFF  155648     // __half2[256]      1024   ((m,m) pairs)
#define S2_OFF   156672     // ull[2][128][8]    16384
#define XA2_OFF  173056     // ull[256][8]       16384
#define SU2_OFF  189440     // ull[128][8]       8192
#define MROW_OFF 197632     // float[16]
#define CNT_OFF  197696     // float
#define FU_SMEM  197760

__global__ __launch_bounds__(512, 1)
void k_fused(const float* __restrict__ node,
             const float* __restrict__ pos,
             const float* __restrict__ mask,
             const float* __restrict__ We1,
             const float* __restrict__ We2,
             const float* __restrict__ be2,
             const float* __restrict__ Wn1,
             const float* __restrict__ bn1,
             const float* __restrict__ Wn2,
             const float* __restrict__ bn2,
             float* __restrict__ out) {
    extern __shared__ __align__(16) char smem[];
    float*   QSM   = (float*)(smem + QSM_OFF);
    float*   BSM   = (float*)(smem + BSM_OFF);
    ull*     DSM2P = (ull*)(smem + DSM_OFF);     // [ip][j] = (d[2ip][j], d[2ip+1][j])
    __half2* MSMH  = (__half2*)(smem + MSM_OFF); // [j] = (m_j, m_j)
    ull*     S2    = (ull*)(smem + S2_OFF);      // [jh][e][ip]
    ull*     XA2   = (ull*)(smem + XA2_OFF);
    ull*     SU2   = (ull*)(smem + SU2_OFF);
    float*   MROW  = (float*)(smem + MROW_OFF);
    float*   CNT   = (float*)(smem + CNT_OFF);

    int i0 = blockIdx.x * TIF;
    int b  = blockIdx.y;
    int tid = threadIdx.x;
    int row0 = b * NN + i0;

    // ---------------- prologue ----------------
    {
        const float4* qsrc = (const float4*)&g_Q[b * NN * HH];
#pragma unroll
        for (int i = 0; i < 16; i++)
            ((float4*)QSM)[tid + i * 512] = qsrc[tid + i * 512];
        const float4* bsrc = (const float4*)&g_P[row0 * HH];
        ((float4*)BSM)[tid] = bsrc[tid];
    }
    {
#pragma unroll
        for (int t = 0; t < 2; t++) {
            int idx = tid + t * 512;
            int e = idx & 127, p = idx >> 7;
            XA2[e * 8 + p] = pack2(node[(row0 + 2 * p) * HH + e],
                                   node[(row0 + 2 * p + 1) * HH + e]);
        }
    }
    {   // dist row-pair tile: 8 ip x 256 j
#pragma unroll
        for (int t = 0; t < 4; t++) {
            int idx = tid + t * 512;
            int ip = idx >> 8, jl = idx & 255;
            const float* p0 = &pos[(row0 + 2 * ip) * 3];
            const float* p1 = &pos[(row0 + 2 * ip + 1) * 3];
            const float* pj = &pos[(b * NN + jl) * 3];
            float jx = pj[0], jy = pj[1], jz = pj[2];
            float dx0 = p0[0] - jx, dy0 = p0[1] - jy, dz0 = p0[2] - jz;
            float dx1 = p1[0] - jx, dy1 = p1[1] - jy, dz1 = p1[2] - jz;
            float s0 = fmaf(dx0, dx0, fmaf(dy0, dy0, dz0 * dz0));
            float s1 = fmaf(dx1, dx1, fmaf(dy1, dy1, dz1 * dz1));
            float d0 = (s0 > 0.0f) ? sqrtfast(s0) : 0.0f;
            float d1 = (s1 > 0.0f) ? sqrtfast(s1) : 0.0f;
            DSM2P[ip * 256 + jl] = pack2(d0, d1);
        }
    }
    if (tid < 256) {
        float m = mask[b * NN + tid];
        MSMH[tid] = __floats2half2_rn(m, m);
    }
    if (tid < 16) MROW[tid] = mask[row0 + tid];
    if (tid < 32) {
        float c = 0.0f;
#pragma unroll
        for (int m = 0; m < 8; m++) c += mask[b * NN + tid * 8 + m];
#pragma unroll
        for (int o = 16; o; o >>= 1) c += __shfl_xor_sync(0xffffffffu, c, o);
        if (tid == 0) *CNT = c;
    }
    __syncthreads();

    // ---------------- main edge loop (fp16 silu, j-half split) ----------------
    {
        int jh = tid >> 8;                // warp-uniform j half
        int ip = (tid >> 5) & 7;          // row-pair (rows 2ip, 2ip+1)
        int k0 = (tid & 31) * 4;          // k-quad

        ull wd2[4], base2[4], acc2[4];
#pragma unroll
        for (int d = 0; d < 4; d++) {
            float w = 0.5f * We1[2 * HH * HH + k0 + d];
            wd2[d] = pack2(w, w);
            base2[d] = pack2(BSM[(2 * ip) * HH + k0 + d],
                             BSM[(2 * ip + 1) * HH + k0 + d]);
            acc2[d] = 0ULL;
        }
        const ull*     drow  = &DSM2P[ip * 256 + jh * 128];
        const __half2* msrc  = &MSMH[jh * 128];
        const float*   qbase = &QSM[jh * 128 * HH + k0];

#pragma unroll 1
        for (int jt = 0; jt < 128; jt += 8) {
            __half2 macc[4];
#pragma unroll
            for (int d = 0; d < 4; d++) macc[d] = __floats2half2_rn(0.0f, 0.0f);
#pragma unroll
            for (int u = 0; u < 8; u++) {
                int jl = jt + u;
                ull dist2 = drow[jl];
                __half2 m2 = msrc[jl];
                float4 q = *(const float4*)&qbase[jl * HH];
                ull qv[4] = {pack2(q.x, q.x), pack2(q.y, q.y),
                             pack2(q.z, q.z), pack2(q.w, q.w)};
#pragma unroll
                for (int d = 0; d < 4; d++) {
                    ull h2 = fma2(dist2, wd2[d], add2(base2[d], qv[d]));  // h/2 (f32)
                    float hl, hh; unpack2(h2, hl, hh);
                    __half2 hf = __floats2half2_rn(hl, hh);
                    __half2 t2 = tanh2h(hf);
                    __half2 s2 = __hfma2(hf, t2, hf);      // silu(h) = h2*(1+t)
                    macc[d] = __hfma2(m2, s2, macc[d]);    // += m * silu (fp16, 8 terms)
                }
            }
#pragma unroll
            for (int d = 0; d < 4; d++) {                  // flush to f32
                float2 f = __half22float2(macc[d]);
                acc2[d] = add2(acc2[d], pack2(f.x, f.y));
            }
        }
#pragma unroll
        for (int d = 0; d < 4; d++)
            S2[jh * (HH * 8) + (k0 + d) * 8 + ip] = acc2[d];
    }
    __syncthreads();

    // ---------------- tail: 3 GEMV stages (2 pairs per thread) ----------------
    int k = tid & 127;
    int g = tid >> 7;                     // pair group: pairs 2g, 2g+1
    float cnt = *CNT;

    // Stage A: agg = m*(S@We2 + cnt*be2)/max(m*cnt,1) -> XA2[HH+k][pr]
    {
        ull acc2[2] = {0ULL, 0ULL};
        const float* W = We2 + k;
        float w0[16], w1[16];
#pragma unroll
        for (int e = 0; e < 16; e++) w0[e] = W[e * HH];
#pragma unroll
        for (int c = 0; c < 8; c++) {
            float* wc = (c & 1) ? w1 : w0;
            float* wn = (c & 1) ? w0 : w1;
            if (c < 7) {
#pragma unroll
                for (int e = 0; e < 16; e++) wn[e] = W[((c + 1) * 16 + e) * HH];
            }
#pragma unroll
            for (int e = 0; e < 16; e++) {
                ull w2 = pack2(wc[e], wc[e]);
#pragma unroll
                for (int pp = 0; pp < 2; pp++) {
                    int idx = (c * 16 + e) * 8 + 2 * g + pp;
                    ull sv = add2(S2[idx], S2[HH * 8 + idx]);
                    acc2[pp] = fma2(sv, w2, acc2[pp]);
                }
            }
        }
        float be2k = be2[k];
#pragma unroll
        for (int pp = 0; pp < 2; pp++) {
            int pr = 2 * g + pp;
            float lo, hi; unpack2(acc2[pp], lo, hi);
            float m0 = MROW[2 * pr], m1 = MROW[2 * pr + 1];
            float a0 = m0 * (lo + cnt * be2k) / fmaxf(m0 * cnt, 1.0f);
            float a1 = m1 * (hi + cnt * be2k) / fmaxf(m1 * cnt, 1.0f);
            XA2[(HH + k) * 8 + pr] = pack2(a0, a1);
        }
    }
    __syncthreads();

    // Stage B: u1 = silu([X|A] @ Wn1 + bn1) -> SU2
    {
        float b1 = bn1[k];
        ull acc2[2] = {pack2(b1, b1), pack2(b1, b1)};
        const float* W = Wn1 + k;
        float w0[16], w1[16];
#pragma unroll
        for (int e = 0; e < 16; e++) w0[e] = W[e * HH];
#pragma unroll
        for (int c = 0; c < 16; c++) {
            float* wc = (c & 1) ? w1 : w0;
            float* wn = (c & 1) ? w0 : w1;
            if (c < 15) {
#pragma unroll
                for (int e = 0; e < 16; e++) wn[e] = W[((c + 1) * 16 + e) * HH];
            }
#pragma unroll
            for (int e = 0; e < 16; e++) {
                ull w2 = pack2(wc[e], wc[e]);
#pragma unroll
                for (int pp = 0; pp < 2; pp++) {
                    ull xv = XA2[(c * 16 + e) * 8 + 2 * g + pp];
                    acc2[pp] = fma2(xv, w2, acc2[pp]);
                }
            }
        }
#pragma unroll
        for (int pp = 0; pp < 2; pp++) {
            int pr = 2 * g + pp;
            float lo, hi; unpack2(acc2[pp], lo, hi);
            SU2[k * 8 + pr] = pack2(lo * fast_sigmoid(lo), hi * fast_sigmoid(hi));
        }
    }
    __syncthreads();

    // Stage C: out = node + m * (u1 @ Wn2 + bn2)
    {
        float b2 = bn2[k];
        ull acc2[2] = {pack2(b2, b2), pack2(b2, b2)};
        const float* W = Wn2 + k;
        float w0[16], w1[16];
#pragma unroll
        for (int e = 0; e < 16; e++) w0[e] = W[e * HH];
#pragma unroll
        for (int c = 0; c < 8; c++) {
            float* wc = (c & 1) ? w1 : w0;
            float* wn = (c & 1) ? w0 : w1;
            if (c < 7) {
#pragma unroll
                for (int e = 0; e < 16; e++) wn[e] = W[((c + 1) * 16 + e) * HH];
            }
#pragma unroll
            for (int e = 0; e < 16; e++) {
                ull w2 = pack2(wc[e], wc[e]);
#pragma unroll
                for (int pp = 0; pp < 2; pp++) {
                    ull uv = SU2[(c * 16 + e) * 8 + 2 * g + pp];
                    acc2[pp] = fma2(uv, w2, acc2[pp]);
                }
            }
        }
#pragma unroll
        for (int pp = 0; pp < 2; pp++) {
            int pr = 2 * g + pp;
            float lo, hi; unpack2(acc2[pp], lo, hi);
            float x0, x1; unpack2(XA2[k * 8 + pr], x0, x1);
            out[(row0 + 2 * pr) * HH + k] = x0 + MROW[2 * pr] * lo;
            out[(row0 + 2 * pr + 1) * HH + k] = x1 + MROW[2 * pr + 1] * hi;
        }
    }
}

extern "C" void kernel_launch(void* const* d_in, const int* in_sizes, int n_in,
                              void* d_out, int out_size) {
    (void)in_sizes; (void)n_in; (void)out_size;
    const float* node = (const float*)d_in[0];
    const float* pos  = (const float*)d_in[1];
    const float* mask = (const float*)d_in[2];
    const float* We1  = (const float*)d_in[3];
    const float* be1  = (const float*)d_in[4];
    const float* We2  = (const float*)d_in[5];
    const float* be2  = (const float*)d_in[6];
    const float* Wn1  = (const float*)d_in[7];
    const float* bn1  = (const float*)d_in[8];
    const float* Wn2  = (const float*)d_in[9];
    const float* bn2  = (const float*)d_in[10];
    float* out = (float*)d_out;

    cudaFuncSetAttribute(k_pq, cudaFuncAttributeMaxDynamicSharedMemorySize, PQ_SMEM);
    cudaFuncSetAttribute(k_fused, cudaFuncAttributeMaxDynamicSharedMemorySize, FU_SMEM);

    k_pq<<<ROWS / 16, 512, PQ_SMEM>>>(node, We1, be1);
    k_fused<<<dim3(NN / TIF, BB), 512, FU_SMEM>>>(node, pos, mask, We1, We2, be2,
                                                  Wn1, bn1, Wn2, bn2, out);
}

// round 12
// speedup vs baseline: 1.0926x; 1.0926x over previous
#include <cuda_runtime.h>
#include <cuda_bf16.h>
#include <cuda_fp16.h>

// Problem constants (B=8, N=256, H=128)
#define BB 8
#define NN 256
#define HH 128
#define ROWS (BB * NN)        // 2048
#define TIF 16                // i-rows per fused CTA

typedef unsigned long long ull;

// Scratch (allocation-free rule: __device__ globals)
// g_P = 0.5*(node@We1a + be1); g_Q = 0.5*(node@We1b)  (pre-halved for tanh-silu)
__device__ float g_P[ROWS * HH];
__device__ float g_Q[ROWS * HH];

// ---------------- packed f32x2 + MUFU helpers ----------------
__device__ __forceinline__ ull fma2(ull a, ull b, ull c) {
    ull d; asm("fma.rn.f32x2 %0, %1, %2, %3;" : "=l"(d) : "l"(a), "l"(b), "l"(c)); return d;
}
__device__ __forceinline__ ull add2(ull a, ull b) {
    ull d; asm("add.rn.f32x2 %0, %1, %2;" : "=l"(d) : "l"(a), "l"(b)); return d;
}
__device__ __forceinline__ ull mul2(ull a, ull b) {
    ull d; asm("mul.rn.f32x2 %0, %1, %2;" : "=l"(d) : "l"(a), "l"(b)); return d;
}
__device__ __forceinline__ ull pack2(float lo, float hi) {
    ull d; asm("mov.b64 %0, {%1, %2};" : "=l"(d) : "f"(lo), "f"(hi)); return d;
}
__device__ __forceinline__ void unpack2(ull v, float& lo, float& hi) {
    asm("mov.b64 {%0, %1}, %2;" : "=f"(lo), "=f"(hi) : "l"(v));
}
__device__ __forceinline__ float sqrtfast(float x) {
    float y; asm("sqrt.approx.f32 %0, %1;" : "=f"(y) : "f"(x)); return y;
}
__device__ __forceinline__ float fast_sigmoid(float x) {
    float e; asm("ex2.approx.f32 %0, %1;" : "=f"(e) : "f"(-1.4426950408889634f * x));
    float r; asm("rcp.approx.f32 %0, %1;" : "=f"(r) : "f"(1.0f + e));
    return r;
}
// tanh on both fp16 lanes, one MUFU op
__device__ __forceinline__ __half2 tanh2h(__half2 h) {
    unsigned u = *reinterpret_cast<unsigned*>(&h);
    asm("tanh.approx.f16x2 %0, %0;" : "+r"(u));
    return *reinterpret_cast<__half2*>(&u);
}

// ---- tail GEMV helpers: direct-array double buffering (NO pointer swap) ----
__device__ __forceinline__ void loadw16(float (&buf)[16], const float* Wk, int c) {
#pragma unroll
    for (int e = 0; e < 16; e++) buf[e] = Wk[(c * 16 + e) * HH];
}
__device__ __forceinline__ void gemv_chunk(const float (&w)[16], const ull* src,
                                           int c, int g, ull (&acc)[2]) {
#pragma unroll
    for (int e = 0; e < 16; e++) {
        ull w2 = pack2(w[e], w[e]);
#pragma unroll
        for (int pp = 0; pp < 2; pp++)
            acc[pp] = fma2(src[(c * 16 + e) * 8 + 2 * g + pp], w2, acc[pp]);
    }
}

// ---------------------------------------------------------------------------
// Kernel 1: P' = 0.5*(node@We1a + be1) ; Q' = 0.5*(node@We1b)
// grid 128 x 512 thr, 16 rows/CTA. ENTIRE We1[0:256] (128 KB) staged to smem
// once; inner loop is pure LDS + fma2.
// ---------------------------------------------------------------------------
#define PQ_SMEM (131072 + 8192)
__global__ __launch_bounds__(512, 1)
void k_pq(const float* __restrict__ node,
          const float* __restrict__ We1,
          const float* __restrict__ be1) {
    extern __shared__ __align__(16) char smem_pq[];
    float* wsm = (float*)smem_pq;                 // [e 0..255][k]  128 KB
    ull*   xs2 = (ull*)(smem_pq + 131072);        // [e][p<8]       8 KB

    int row0 = blockIdx.x * 16;
    int tid = threadIdx.x;
    int k = tid & 127;
    int half = (tid >> 7) & 1;
    int rg = tid >> 8;

    {
        const float4* wsrc = (const float4*)We1;
        float4* wdst = (float4*)wsm;
#pragma unroll
        for (int i = 0; i < 16; i++) wdst[tid + i * 512] = wsrc[tid + i * 512];
    }
    {
#pragma unroll
        for (int t = 0; t < 2; t++) {
            int idx = tid + t * 512;
            int e = idx & 127, p = idx >> 7;
            xs2[e * 8 + p] = pack2(node[(row0 + 2 * p) * HH + e],
                                   node[(row0 + 2 * p + 1) * HH + e]);
        }
    }
    __syncthreads();

    const float* W = wsm + half * (HH * HH) + k;
    float bv = half ? 0.0f : be1[k];
    ull acc2[4];
#pragma unroll
    for (int p = 0; p < 4; p++) acc2[p] = pack2(bv, bv);

#pragma unroll 8
    for (int e = 0; e < HH; e++) {
        float w = W[e * HH];
        ull w2 = pack2(w, w);
        ulonglong2 xa = *(const ulonglong2*)&xs2[e * 8 + rg * 4];
        ulonglong2 xb = *(const ulonglong2*)&xs2[e * 8 + rg * 4 + 2];
        acc2[0] = fma2(xa.x, w2, acc2[0]);
        acc2[1] = fma2(xa.y, w2, acc2[1]);
        acc2[2] = fma2(xb.x, w2, acc2[2]);
        acc2[3] = fma2(xb.y, w2, acc2[3]);
    }

    float* dst = half ? g_Q : g_P;
    ull hc = pack2(0.5f, 0.5f);
#pragma unroll
    for (int p = 0; p < 4; p++) {
        float lo, hi; unpack2(mul2(acc2[p], hc), lo, hi);
        int pr = rg * 4 + p;
        dst[(row0 + 2 * pr) * HH + k] = lo;
        dst[(row0 + 2 * pr + 1) * HH + k] = hi;
    }
}

// ---------------------------------------------------------------------------
// Fused kernel: edge aggregation + agg scale + node MLP + residual.
// grid (N/TIF, B) = 128 CTAs, 512 threads.
// Edge: thread = (jh, row-pair ip, k-quad), fp16 silu (unchanged from R11).
// Tail: 3 GEMV stages with explicit even/odd register double-buffered weights
// (no pointer indirection -> no local-memory demotion). S halves pre-merged.
// ---------------------------------------------------------------------------
#define QSM_OFF  0          // float[256][128]   131072
#define BSM_OFF  131072     // float[16][128]    8192
#define DSM_OFF  139264     // ull[8][256]       16384  (dist row-pairs)
#define MSM_OFF  155648     // __half2[256]      1024   ((m,m) pairs)
#define S2_OFF   156672     // ull[2][128][8]    16384
#define XA2_OFF  173056     // ull[256][8]       16384
#define SU2_OFF  189440     // ull[128][8]       8192
#define MROW_OFF 197632     // float[16]
#define CNT_OFF  197696     // float
#define FU_SMEM  197760

__global__ __launch_bounds__(512, 1)
void k_fused(const float* __restrict__ node,
             const float* __restrict__ pos,
             const float* __restrict__ mask,
             const float* __restrict__ We1,
             const float* __restrict__ We2,
             const float* __restrict__ be2,
             const float* __restrict__ Wn1,
             const float* __restrict__ bn1,
             const float* __restrict__ Wn2,
             const float* __restrict__ bn2,
             float* __restrict__ out) {
    extern __shared__ __align__(16) char smem[];
    float*   QSM   = (float*)(smem + QSM_OFF);
    float*   BSM   = (float*)(smem + BSM_OFF);
    ull*     DSM2P = (ull*)(smem + DSM_OFF);     // [ip][j] = (d[2ip][j], d[2ip+1][j])
    __half2* MSMH  = (__half2*)(smem + MSM_OFF); // [j] = (m_j, m_j)
    ull*     S2    = (ull*)(smem + S2_OFF);      // [jh][e][ip]
    ull*     XA2   = (ull*)(smem + XA2_OFF);
    ull*     SU2   = (ull*)(smem + SU2_OFF);
    float*   MROW  = (float*)(smem + MROW_OFF);
    float*   CNT   = (float*)(smem + CNT_OFF);

    int i0 = blockIdx.x * TIF;
    int b  = blockIdx.y;
    int tid = threadIdx.x;
    int row0 = b * NN + i0;

    // ---------------- prologue ----------------
    {
        const float4* qsrc = (const float4*)&g_Q[b * NN * HH];
#pragma unroll
        for (int i = 0; i < 16; i++)
            ((float4*)QSM)[tid + i * 512] = qsrc[tid + i * 512];
        const float4* bsrc = (const float4*)&g_P[row0 * HH];
        ((float4*)BSM)[tid] = bsrc[tid];
    }
    {
#pragma unroll
        for (int t = 0; t < 2; t++) {
            int idx = tid + t * 512;
            int e = idx & 127, p = idx >> 7;
            XA2[e * 8 + p] = pack2(node[(row0 + 2 * p) * HH + e],
                                   node[(row0 + 2 * p + 1) * HH + e]);
        }
    }
    {   // dist row-pair tile: 8 ip x 256 j
#pragma unroll
        for (int t = 0; t < 4; t++) {
            int idx = tid + t * 512;
            int ip = idx >> 8, jl = idx & 255;
            const float* p0 = &pos[(row0 + 2 * ip) * 3];
            const float* p1 = &pos[(row0 + 2 * ip + 1) * 3];
            const float* pj = &pos[(b * NN + jl) * 3];
            float jx = pj[0], jy = pj[1], jz = pj[2];
            float dx0 = p0[0] - jx, dy0 = p0[1] - jy, dz0 = p0[2] - jz;
            float dx1 = p1[0] - jx, dy1 = p1[1] - jy, dz1 = p1[2] - jz;
            float s0 = fmaf(dx0, dx0, fmaf(dy0, dy0, dz0 * dz0));
            float s1 = fmaf(dx1, dx1, fmaf(dy1, dy1, dz1 * dz1));
            float d0 = (s0 > 0.0f) ? sqrtfast(s0) : 0.0f;
            float d1 = (s1 > 0.0f) ? sqrtfast(s1) : 0.0f;
            DSM2P[ip * 256 + jl] = pack2(d0, d1);
        }
    }
    if (tid < 256) {
        float m = mask[b * NN + tid];
        MSMH[tid] = __floats2half2_rn(m, m);
    }
    if (tid < 16) MROW[tid] = mask[row0 + tid];
    if (tid < 32) {
        float c = 0.0f;
#pragma unroll
        for (int m = 0; m < 8; m++) c += mask[b * NN + tid * 8 + m];
#pragma unroll
        for (int o = 16; o; o >>= 1) c += __shfl_xor_sync(0xffffffffu, c, o);
        if (tid == 0) *CNT = c;
    }
    __syncthreads();

    // ---------------- main edge loop (fp16 silu, j-half split) ----------------
    {
        int jh = tid >> 8;                // warp-uniform j half
        int ip = (tid >> 5) & 7;          // row-pair (rows 2ip, 2ip+1)
        int k0 = (tid & 31) * 4;          // k-quad

        ull wd2[4], base2[4], acc2[4];
#pragma unroll
        for (int d = 0; d < 4; d++) {
            float w = 0.5f * We1[2 * HH * HH + k0 + d];
            wd2[d] = pack2(w, w);
            base2[d] = pack2(BSM[(2 * ip) * HH + k0 + d],
                             BSM[(2 * ip + 1) * HH + k0 + d]);
            acc2[d] = 0ULL;
        }
        const ull*     drow  = &DSM2P[ip * 256 + jh * 128];
        const __half2* msrc  = &MSMH[jh * 128];
        const float*   qbase = &QSM[jh * 128 * HH + k0];

#pragma unroll 1
        for (int jt = 0; jt < 128; jt += 8) {
            __half2 macc[4];
#pragma unroll
            for (int d = 0; d < 4; d++) macc[d] = __floats2half2_rn(0.0f, 0.0f);
#pragma unroll
            for (int u = 0; u < 8; u++) {
                int jl = jt + u;
                ull dist2 = drow[jl];
                __half2 m2 = msrc[jl];
                float4 q = *(const float4*)&qbase[jl * HH];
                ull qv[4] = {pack2(q.x, q.x), pack2(q.y, q.y),
                             pack2(q.z, q.z), pack2(q.w, q.w)};
#pragma unroll
                for (int d = 0; d < 4; d++) {
                    ull h2 = fma2(dist2, wd2[d], add2(base2[d], qv[d]));  // h/2 (f32)
                    float hl, hh; unpack2(h2, hl, hh);
                    __half2 hf = __floats2half2_rn(hl, hh);
                    __half2 t2 = tanh2h(hf);
                    __half2 s2 = __hfma2(hf, t2, hf);      // silu(h) = h2*(1+t)
                    macc[d] = __hfma2(m2, s2, macc[d]);    // += m * silu
                }
            }
#pragma unroll
            for (int d = 0; d < 4; d++) {                  // flush to f32
                float2 f = __half22float2(macc[d]);
                acc2[d] = add2(acc2[d], pack2(f.x, f.y));
            }
        }
#pragma unroll
        for (int d = 0; d < 4; d++)
            S2[jh * (HH * 8) + (k0 + d) * 8 + ip] = acc2[d];
    }
    __syncthreads();

    // merge the two j-half S buffers in place (saves LDS+add in stage A)
    {
#pragma unroll
        for (int t = 0; t < 2; t++) {
            int i = tid + t * 512;
            S2[i] = add2(S2[i], S2[HH * 8 + i]);
        }
    }
    __syncthreads();

    // ---------------- tail: 3 GEMV stages (2 pairs per thread) ----------------
    int k = tid & 127;
    int g = tid >> 7;                     // pair group: pairs 2g, 2g+1
    float cnt = *CNT;

    // Stage A: agg = m*(S@We2 + cnt*be2)/max(m*cnt,1) -> XA2[HH+k][pr]
    {
        ull acc2[2] = {0ULL, 0ULL};
        const float* W = We2 + k;
        float w0[16], w1[16];
        loadw16(w0, W, 0);
#pragma unroll
        for (int c = 0; c < 8; c += 2) {
            loadw16(w1, W, c + 1);
            gemv_chunk(w0, S2, c, g, acc2);
            if (c + 2 < 8) loadw16(w0, W, c + 2);
            gemv_chunk(w1, S2, c + 1, g, acc2);
        }
        float be2k = be2[k];
#pragma unroll
        for (int pp = 0; pp < 2; pp++) {
            int pr = 2 * g + pp;
            float lo, hi; unpack2(acc2[pp], lo, hi);
            float m0 = MROW[2 * pr], m1 = MROW[2 * pr + 1];
            float a0 = m0 * (lo + cnt * be2k) / fmaxf(m0 * cnt, 1.0f);
            float a1 = m1 * (hi + cnt * be2k) / fmaxf(m1 * cnt, 1.0f);
            XA2[(HH + k) * 8 + pr] = pack2(a0, a1);
        }
    }
    __syncthreads();

    // Stage B: u1 = silu([X|A] @ Wn1 + bn1) -> SU2
    {
        float b1 = bn1[k];
        ull acc2[2] = {pack2(b1, b1), pack2(b1, b1)};
        const float* W = Wn1 + k;
        float w0[16], w1[16];
        loadw16(w0, W, 0);
#pragma unroll
        for (int c = 0; c < 16; c += 2) {
            loadw16(w1, W, c + 1);
            gemv_chunk(w0, XA2, c, g, acc2);
            if (c + 2 < 16) loadw16(w0, W, c + 2);
            gemv_chunk(w1, XA2, c + 1, g, acc2);
        }
#pragma unroll
        for (int pp = 0; pp < 2; pp++) {
            int pr = 2 * g + pp;
            float lo, hi; unpack2(acc2[pp], lo, hi);
            SU2[k * 8 + pr] = pack2(lo * fast_sigmoid(lo), hi * fast_sigmoid(hi));
        }
    }
    __syncthreads();

    // Stage C: out = node + m * (u1 @ Wn2 + bn2)
    {
        float b2 = bn2[k];
        ull acc2[2] = {pack2(b2, b2), pack2(b2, b2)};
        const float* W = Wn2 + k;
        float w0[16], w1[16];
        loadw16(w0, W, 0);
#pragma unroll
        for (int c = 0; c < 8; c += 2) {
            loadw16(w1, W, c + 1);
            gemv_chunk(w0, SU2, c, g, acc2);
            if (c + 2 < 8) loadw16(w0, W, c + 2);
            gemv_chunk(w1, SU2, c + 1, g, acc2);
        }
#pragma unroll
        for (int pp = 0; pp < 2; pp++) {
            int pr = 2 * g + pp;
            float lo, hi; unpack2(acc2[pp], lo, hi);
            float x0, x1; unpack2(XA2[k * 8 + pr], x0, x1);
            out[(row0 + 2 * pr) * HH + k] = x0 + MROW[2 * pr] * lo;
            out[(row0 + 2 * pr + 1) * HH + k] = x1 + MROW[2 * pr + 1] * hi;
        }
    }
}

extern "C" void kernel_launch(void* const* d_in, const int* in_sizes, int n_in,
                              void* d_out, int out_size) {
    (void)in_sizes; (void)n_in; (void)out_size;
    const float* node = (const float*)d_in[0];
    const float* pos  = (const float*)d_in[1];
    const float* mask = (const float*)d_in[2];
    const float* We1  = (const float*)d_in[3];
    const float* be1  = (const float*)d_in[4];
    const float* We2  = (const float*)d_in[5];
    const float* be2  = (const float*)d_in[6];
    const float* Wn1  = (const float*)d_in[7];
    const float* bn1  = (const float*)d_in[8];
    const float* Wn2  = (const float*)d_in[9];
    const float* bn2  = (const float*)d_in[10];
    float* out = (float*)d_out;

    cudaFuncSetAttribute(k_pq, cudaFuncAttributeMaxDynamicSharedMemorySize, PQ_SMEM);
    cudaFuncSetAttribute(k_fused, cudaFuncAttributeMaxDynamicSharedMemorySize, FU_SMEM);

    k_pq<<<ROWS / 16, 512, PQ_SMEM>>>(node, We1, be1);
    k_fused<<<dim3(NN / TIF, BB), 512, FU_SMEM>>>(node, pos, mask, We1, We2, be2,
                                                  Wn1, bn1, Wn2, bn2, out);
}

// round 13
// speedup vs baseline: 1.0978x; 1.0048x over previous
#include <cuda_runtime.h>
#include <cuda_bf16.h>
#include <cuda_fp16.h>

// Problem constants (B=8, N=256, H=128)
#define BB 8
#define NN 256
#define HH 128
#define ROWS (BB * NN)        // 2048
#define TIF 16                // i-rows per fused CTA

typedef unsigned long long ull;
typedef unsigned int uint;

// Scratch (allocation-free rule: __device__ globals)
// g_P  = 0.5*(node@We1a + be1)  (f32)
// g_Qh = 0.5*(node@We1b) as duplicated half2 (q,q) per element
__device__ float g_P[ROWS * HH];
__device__ uint  g_Qh[ROWS * HH];

// ---------------- packed f32x2 / fp16 helpers ----------------
__device__ __forceinline__ ull fma2(ull a, ull b, ull c) {
    ull d; asm("fma.rn.f32x2 %0, %1, %2, %3;" : "=l"(d) : "l"(a), "l"(b), "l"(c)); return d;
}
__device__ __forceinline__ ull add2(ull a, ull b) {
    ull d; asm("add.rn.f32x2 %0, %1, %2;" : "=l"(d) : "l"(a), "l"(b)); return d;
}
__device__ __forceinline__ ull mul2(ull a, ull b) {
    ull d; asm("mul.rn.f32x2 %0, %1, %2;" : "=l"(d) : "l"(a), "l"(b)); return d;
}
__device__ __forceinline__ ull pack2(float lo, float hi) {
    ull d; asm("mov.b64 %0, {%1, %2};" : "=l"(d) : "f"(lo), "f"(hi)); return d;
}
__device__ __forceinline__ void unpack2(ull v, float& lo, float& hi) {
    asm("mov.b64 {%0, %1}, %2;" : "=f"(lo), "=f"(hi) : "l"(v));
}
__device__ __forceinline__ float sqrtfast(float x) {
    float y; asm("sqrt.approx.f32 %0, %1;" : "=f"(y) : "f"(x)); return y;
}
__device__ __forceinline__ float fast_sigmoid(float x) {
    float e; asm("ex2.approx.f32 %0, %1;" : "=f"(e) : "f"(-1.4426950408889634f * x));
    float r; asm("rcp.approx.f32 %0, %1;" : "=f"(r) : "f"(1.0f + e));
    return r;
}
__device__ __forceinline__ __half2 tanh2h(__half2 h) {
    unsigned u = *reinterpret_cast<unsigned*>(&h);
    asm("tanh.approx.f16x2 %0, %0;" : "+r"(u));
    return *reinterpret_cast<__half2*>(&u);
}
__device__ __forceinline__ __half2 u2h2(uint u) { return *reinterpret_cast<__half2*>(&u); }
__device__ __forceinline__ uint h2u(__half2 h) { return *reinterpret_cast<uint*>(&h); }

// ---- tail GEMV helpers: direct-array double buffering (NO pointer swap) ----
__device__ __forceinline__ void loadw16(float (&buf)[16], const float* Wk, int c) {
#pragma unroll
    for (int e = 0; e < 16; e++) buf[e] = Wk[(c * 16 + e) * HH];
}
__device__ __forceinline__ void gemv_chunk(const float (&w)[16], const ull* src,
                                           int c, int g, ull (&acc)[2]) {
#pragma unroll
    for (int e = 0; e < 16; e++) {
        ull w2 = pack2(w[e], w[e]);
#pragma unroll
        for (int pp = 0; pp < 2; pp++)
            acc[pp] = fma2(src[(c * 16 + e) * 8 + 2 * g + pp], w2, acc[pp]);
    }
}

// ---------------------------------------------------------------------------
// Kernel 1: P' = 0.5*(node@We1a + be1) (f32) ; Q' = 0.5*(node@We1b) (half2 dup)
// grid 128 x 512 thr, 16 rows/CTA; full We1 staged in smem; LDS+fma2 loop.
// ---------------------------------------------------------------------------
#define PQ_SMEM (131072 + 8192)
__global__ __launch_bounds__(512, 1)
void k_pq(const float* __restrict__ node,
          const float* __restrict__ We1,
          const float* __restrict__ be1) {
    extern __shared__ __align__(16) char smem_pq[];
    float* wsm = (float*)smem_pq;                 // [e 0..255][k]  128 KB
    ull*   xs2 = (ull*)(smem_pq + 131072);        // [e][p<8]       8 KB

    int row0 = blockIdx.x * 16;
    int tid = threadIdx.x;
    int k = tid & 127;
    int half = (tid >> 7) & 1;
    int rg = tid >> 8;

    {
        const float4* wsrc = (const float4*)We1;
        float4* wdst = (float4*)wsm;
#pragma unroll
        for (int i = 0; i < 16; i++) wdst[tid + i * 512] = wsrc[tid + i * 512];
    }
    {
#pragma unroll
        for (int t = 0; t < 2; t++) {
            int idx = tid + t * 512;
            int e = idx & 127, p = idx >> 7;
            xs2[e * 8 + p] = pack2(node[(row0 + 2 * p) * HH + e],
                                   node[(row0 + 2 * p + 1) * HH + e]);
        }
    }
    __syncthreads();

    const float* W = wsm + half * (HH * HH) + k;
    float bv = half ? 0.0f : be1[k];
    ull acc2[4];
#pragma unroll
    for (int p = 0; p < 4; p++) acc2[p] = pack2(bv, bv);

#pragma unroll 8
    for (int e = 0; e < HH; e++) {
        float w = W[e * HH];
        ull w2 = pack2(w, w);
        ulonglong2 xa = *(const ulonglong2*)&xs2[e * 8 + rg * 4];
        ulonglong2 xb = *(const ulonglong2*)&xs2[e * 8 + rg * 4 + 2];
        acc2[0] = fma2(xa.x, w2, acc2[0]);
        acc2[1] = fma2(xa.y, w2, acc2[1]);
        acc2[2] = fma2(xb.x, w2, acc2[2]);
        acc2[3] = fma2(xb.y, w2, acc2[3]);
    }

    ull hc = pack2(0.5f, 0.5f);
    if (half == 0) {
#pragma unroll
        for (int p = 0; p < 4; p++) {
            float lo, hi; unpack2(mul2(acc2[p], hc), lo, hi);
            int pr = rg * 4 + p;
            g_P[(row0 + 2 * pr) * HH + k] = lo;
            g_P[(row0 + 2 * pr + 1) * HH + k] = hi;
        }
    } else {
#pragma unroll
        for (int p = 0; p < 4; p++) {
            float lo, hi; unpack2(mul2(acc2[p], hc), lo, hi);
            int pr = rg * 4 + p;
            g_Qh[(row0 + 2 * pr) * HH + k] = h2u(__floats2half2_rn(lo, lo));
            g_Qh[(row0 + 2 * pr + 1) * HH + k] = h2u(__floats2half2_rn(hi, hi));
        }
    }
}

// ---------------------------------------------------------------------------
// Fused kernel: edge aggregation + agg scale + node MLP + residual.
// grid (N/TIF, B) = 128 CTAs, 512 threads.
// Edge: fp16-native inner loop. thread = (jh, row-pair ip, k-quad).
//   per (jl,d): HFMA2(dist,wd, HADD2(base,q)) -> tanh.f16x2 -> HFMA2 -> HFMA2
//   (5 instrs, no cvt, no packs). macc flushed to f32 every 8 j.
// Tail: R12 form (explicit even/odd double-buffered weights).
// ---------------------------------------------------------------------------
#define QSM_OFF  0          // uint[256][128] (half2 dup)  131072
#define BSM_OFF  131072     // float[16][128]              8192
#define DSM_OFF  139264     // __half2[8][256]             8192   (dist row-pairs)
#define MSM_OFF  147456     // __half2[256]                1024
#define S2_OFF   148480     // ull[2][128][8]              16384
#define XA2_OFF  164864     // ull[256][8]                 16384
#define SU2_OFF  181248     // ull[128][8]                 8192
#define MROW_OFF 189440     // float[16]
#define CNT_OFF  189504     // float
#define FU_SMEM  189568

__global__ __launch_bounds__(512, 1)
void k_fused(const float* __restrict__ node,
             const float* __restrict__ pos,
             const float* __restrict__ mask,
             const float* __restrict__ We1,
             const float* __restrict__ We2,
             const float* __restrict__ be2,
             const float* __restrict__ Wn1,
             const float* __restrict__ bn1,
             const float* __restrict__ Wn2,
             const float* __restrict__ bn2,
             float* __restrict__ out) {
    extern __shared__ __align__(16) char smem[];
    uint*    QSMh  = (uint*)(smem + QSM_OFF);    // [j][k] = half2(q,q)
    float*   BSM   = (float*)(smem + BSM_OFF);
    __half2* DSMH  = (__half2*)(smem + DSM_OFF); // [ip][j] = (d_2ip, d_2ip+1)
    __half2* MSMH  = (__half2*)(smem + MSM_OFF); // [j] = (m,m)
    ull*     S2    = (ull*)(smem + S2_OFF);      // [jh][e][ip]
    ull*     XA2   = (ull*)(smem + XA2_OFF);
    ull*     SU2   = (ull*)(smem + SU2_OFF);
    float*   MROW  = (float*)(smem + MROW_OFF);
    float*   CNT   = (float*)(smem + CNT_OFF);

    int i0 = blockIdx.x * TIF;
    int b  = blockIdx.y;
    int tid = threadIdx.x;
    int row0 = b * NN + i0;

    // ---------------- prologue ----------------
    {
        const float4* qsrc = (const float4*)&g_Qh[b * NN * HH];
#pragma unroll
        for (int i = 0; i < 16; i++)
            ((float4*)QSMh)[tid + i * 512] = qsrc[tid + i * 512];
        const float4* bsrc = (const float4*)&g_P[row0 * HH];
        ((float4*)BSM)[tid] = bsrc[tid];
    }
    {
#pragma unroll
        for (int t = 0; t < 2; t++) {
            int idx = tid + t * 512;
            int e = idx & 127, p = idx >> 7;
            XA2[e * 8 + p] = pack2(node[(row0 + 2 * p) * HH + e],
                                   node[(row0 + 2 * p + 1) * HH + e]);
        }
    }
    {   // dist row-pair tile: 8 ip x 256 j, stored fp16
#pragma unroll
        for (int t = 0; t < 4; t++) {
            int idx = tid + t * 512;
            int ip = idx >> 8, jl = idx & 255;
            const float* p0 = &pos[(row0 + 2 * ip) * 3];
            const float* p1 = &pos[(row0 + 2 * ip + 1) * 3];
            const float* pj = &pos[(b * NN + jl) * 3];
            float jx = pj[0], jy = pj[1], jz = pj[2];
            float dx0 = p0[0] - jx, dy0 = p0[1] - jy, dz0 = p0[2] - jz;
            float dx1 = p1[0] - jx, dy1 = p1[1] - jy, dz1 = p1[2] - jz;
            float s0 = fmaf(dx0, dx0, fmaf(dy0, dy0, dz0 * dz0));
            float s1 = fmaf(dx1, dx1, fmaf(dy1, dy1, dz1 * dz1));
            float d0 = (s0 > 0.0f) ? sqrtfast(s0) : 0.0f;
            float d1 = (s1 > 0.0f) ? sqrtfast(s1) : 0.0f;
            DSMH[ip * 256 + jl] = __floats2half2_rn(d0, d1);
        }
    }
    if (tid < 256) {
        float m = mask[b * NN + tid];
        MSMH[tid] = __floats2half2_rn(m, m);
    }
    if (tid < 16) MROW[tid] = mask[row0 + tid];
    if (tid < 32) {
        float c = 0.0f;
#pragma unroll
        for (int m = 0; m < 8; m++) c += mask[b * NN + tid * 8 + m];
#pragma unroll
        for (int o = 16; o; o >>= 1) c += __shfl_xor_sync(0xffffffffu, c, o);
        if (tid == 0) *CNT = c;
    }
    __syncthreads();

    // ---------------- main edge loop (fp16-native) ----------------
    {
        int jh = tid >> 8;                // warp-uniform j half
        int ip = (tid >> 5) & 7;          // row-pair (rows 2ip, 2ip+1)
        int k0 = (tid & 31) * 4;          // k-quad

        __half2 wd2h[4], base2h[4];
        ull acc2[4];
#pragma unroll
        for (int d = 0; d < 4; d++) {
            float w = 0.5f * We1[2 * HH * HH + k0 + d];
            wd2h[d] = __floats2half2_rn(w, w);
            base2h[d] = __floats2half2_rn(BSM[(2 * ip) * HH + k0 + d],
                                          BSM[(2 * ip + 1) * HH + k0 + d]);
            acc2[d] = 0ULL;
        }
        const __half2* drow  = &DSMH[ip * 256 + jh * 128];
        const __half2* msrc  = &MSMH[jh * 128];
        const uint*    qbase = &QSMh[jh * 128 * HH + k0];

#pragma unroll 1
        for (int jt = 0; jt < 128; jt += 8) {
            __half2 macc[4];
#pragma unroll
            for (int d = 0; d < 4; d++) macc[d] = __floats2half2_rn(0.0f, 0.0f);
#pragma unroll
            for (int u = 0; u < 8; u++) {
                int jl = jt + u;
                __half2 d2 = drow[jl];
                __half2 m2 = msrc[jl];
                uint4 qr = *(const uint4*)&qbase[jl * HH];
                __half2 qh[4] = {u2h2(qr.x), u2h2(qr.y), u2h2(qr.z), u2h2(qr.w)};
#pragma unroll
                for (int d = 0; d < 4; d++) {
                    __half2 hf = __hfma2(d2, wd2h[d], __hadd2(base2h[d], qh[d])); // h/2
                    __half2 t2 = tanh2h(hf);
                    __half2 s2 = __hfma2(hf, t2, hf);      // silu(h) = h2*(1+t)
                    macc[d] = __hfma2(m2, s2, macc[d]);    // += m * silu
                }
            }
#pragma unroll
            for (int d = 0; d < 4; d++) {                  // flush to f32
                float2 f = __half22float2(macc[d]);
                acc2[d] = add2(acc2[d], pack2(f.x, f.y));
            }
        }
#pragma unroll
        for (int d = 0; d < 4; d++)
            S2[jh * (HH * 8) + (k0 + d) * 8 + ip] = acc2[d];
    }
    __syncthreads();

    // merge the two j-half S buffers in place
    {
#pragma unroll
        for (int t = 0; t < 2; t++) {
            int i = tid + t * 512;
            S2[i] = add2(S2[i], S2[HH * 8 + i]);
        }
    }
    __syncthreads();

    // ---------------- tail: 3 GEMV stages (2 pairs per thread) ----------------
    int k = tid & 127;
    int g = tid >> 7;                     // pair group: pairs 2g, 2g+1
    float cnt = *CNT;

    // Stage A: agg = m*(S@We2 + cnt*be2)/max(m*cnt,1) -> XA2[HH+k][pr]
    {
        ull acc2[2] = {0ULL, 0ULL};
        const float* W = We2 + k;
        float w0[16], w1[16];
        loadw16(w0, W, 0);
#pragma unroll
        for (int c = 0; c < 8; c += 2) {
            loadw16(w1, W, c + 1);
            gemv_chunk(w0, S2, c, g, acc2);
            if (c + 2 < 8) loadw16(w0, W, c + 2);
            gemv_chunk(w1, S2, c + 1, g, acc2);
        }
        float be2k = be2[k];
#pragma unroll
        for (int pp = 0; pp < 2; pp++) {
            int pr = 2 * g + pp;
            float lo, hi; unpack2(acc2[pp], lo, hi);
            float m0 = MROW[2 * pr], m1 = MROW[2 * pr + 1];
            float a0 = m0 * (lo + cnt * be2k) / fmaxf(m0 * cnt, 1.0f);
            float a1 = m1 * (hi + cnt * be2k) / fmaxf(m1 * cnt, 1.0f);
            XA2[(HH + k) * 8 + pr] = pack2(a0, a1);
        }
    }
    __syncthreads();

    // Stage B: u1 = silu([X|A] @ Wn1 + bn1) -> SU2
    {
        float b1 = bn1[k];
        ull acc2[2] = {pack2(b1, b1), pack2(b1, b1)};
        const float* W = Wn1 + k;
        float w0[16], w1[16];
        loadw16(w0, W, 0);
#pragma unroll
        for (int c = 0; c < 16; c += 2) {
            loadw16(w1, W, c + 1);
            gemv_chunk(w0, XA2, c, g, acc2);
            if (c + 2 < 16) loadw16(w0, W, c + 2);
            gemv_chunk(w1, XA2, c + 1, g, acc2);
        }
#pragma unroll
        for (int pp = 0; pp < 2; pp++) {
            int pr = 2 * g + pp;
            float lo, hi; unpack2(acc2[pp], lo, hi);
            SU2[k * 8 + pr] = pack2(lo * fast_sigmoid(lo), hi * fast_sigmoid(hi));
        }
    }
    __syncthreads();

    // Stage C: out = node + m * (u1 @ Wn2 + bn2)
    {
        float b2 = bn2[k];
        ull acc2[2] = {pack2(b2, b2), pack2(b2, b2)};
        const float* W = Wn2 + k;
        float w0[16], w1[16];
        loadw16(w0, W, 0);
#pragma unroll
        for (int c = 0; c < 8; c += 2) {
            loadw16(w1, W, c + 1);
            gemv_chunk(w0, SU2, c, g, acc2);
            if (c + 2 < 8) loadw16(w0, W, c + 2);
            gemv_chunk(w1, SU2, c + 1, g, acc2);
        }
#pragma unroll
        for (int pp = 0; pp < 2; pp++) {
            int pr = 2 * g + pp;
            float lo, hi; unpack2(acc2[pp], lo, hi);
            float x0, x1; unpack2(XA2[k * 8 + pr], x0, x1);
            out[(row0 + 2 * pr) * HH + k] = x0 + MROW[2 * pr] * lo;
            out[(row0 + 2 * pr + 1) * HH + k] = x1 + MROW[2 * pr + 1] * hi;
        }
    }
}

extern "C" void kernel_launch(void* const* d_in, const int* in_sizes, int n_in,
                              void* d_out, int out_size) {
    (void)in_sizes; (void)n_in; (void)out_size;
    const float* node = (const float*)d_in[0];
    const float* pos  = (const float*)d_in[1];
    const float* mask = (const float*)d_in[2];
    const float* We1  = (const float*)d_in[3];
    const float* be1  = (const float*)d_in[4];
    const float* We2  = (const float*)d_in[5];
    const float* be2  = (const float*)d_in[6];
    const float* Wn1  = (const float*)d_in[7];
    const float* bn1  = (const float*)d_in[8];
    const float* Wn2  = (const float*)d_in[9];
    const float* bn2  = (const float*)d_in[10];
    float* out = (float*)d_out;

    cudaFuncSetAttribute(k_pq, cudaFuncAttributeMaxDynamicSharedMemorySize, PQ_SMEM);
    cudaFuncSetAttribute(k_fused, cudaFuncAttributeMaxDynamicSharedMemorySize, FU_SMEM);

    k_pq<<<ROWS / 16, 512, PQ_SMEM>>>(node, We1, be1);
    k_fused<<<dim3(NN / TIF, BB), 512, FU_SMEM>>>(node, pos, mask, We1, We2, be2,
                                                  Wn1, bn1, Wn2, bn2, out);
}